// round 15
// baseline (speedup 1.0000x reference)
#include <cuda_runtime.h>
#include <cuda_bf16.h>

// SingleLIFLayer: V <- V + (dt/tau)*(V_reset - V + I); spike = V >= V_th; reset.
// T=1024 steps x N=65536 neurons. Irreducible traffic: 256 MB R + 256 MB W.
//
// V11: ring-4 pipeline. Four 16-step buffers, prefetch distance = 4 half-
// batches (64 steps): consume R[s], then refill R[s] from 64 steps ahead.
// Keeps the measured-optimal 16-load burst grain (32/16/1 -> 92.0/88.5/89.9)
// while raising the per-warp outstanding-load FLOOR from ~16 to ~48
// (Little's law: need ~45 KB in flight/SM for ~30 B/cyc at ~1500-cyc loaded
// latency; V10's burst/drain averaged ~42 KB -> stuck at 72% DRAM).
// Same buffer register count as V10 (64), same 12-cyc serial chain,
// same 1024x64 grid (1.2% tail), same __ldcs/__stcs.

#define LIF_T   1024
#define LIF_N   65536
#define THREADS 64
#define HB      16                 // steps per half-batch (burst grain)
#define NHB     (LIF_T / HB)       // 64 half-batches

__device__ __forceinline__ void load_half(float* __restrict__ dst,
                                          const float* __restrict__ src) {
    #pragma unroll
    for (int k = 0; k < HB; ++k)
        dst[k] = __ldcs(src + k * LIF_N);
}

__device__ __forceinline__ void consume_half(const float* __restrict__ cur,
                                             float& V, float* __restrict__ spb) {
    const float alpha = 0.05f;
    const float decay = 0.95f;
    const float vth   = 1.0f;
    #pragma unroll
    for (int k = 0; k < HB; ++k) {
        float c = alpha * cur[k];             // off-chain FMUL (hoists to load)
        V = fmaf(decay, V, c);                // chain: FFMA
        float s = (V >= vth) ? 1.0f : 0.0f;   // chain: FSET (data)
        __stcs(spb + k * LIF_N, s);
        V = fmaf(-s, V, V);                   // chain: FFMA (s==1 -> exactly 0)
    }
}

__global__ __launch_bounds__(THREADS, 6)
void lif_kernel(const float* __restrict__ in, float* __restrict__ out) {
    const int n = blockIdx.x * THREADS + threadIdx.x;   // neuron index

    float V = 0.0f;   // V_reset = 0

    const float* __restrict__ ip = in  + n;
    float*       __restrict__ sp = out + n;

    float R0[HB], R1[HB], R2[HB], R3[HB];

    // Prologue: fill the ring with half-batches 0..3 (64 loads in flight).
    load_half(R0, ip + 0 * (HB * LIF_N));
    load_half(R1, ip + 1 * (HB * LIF_N));
    load_half(R2, ip + 2 * (HB * LIF_N));
    load_half(R3, ip + 3 * (HB * LIF_N));

    #pragma unroll 1
    for (int hb = 0; hb < NHB; hb += 4) {
        // consume hb+0, refill with hb+4
        consume_half(R0, V, sp + (hb + 0) * (HB * LIF_N));
        if (hb + 4 < NHB) load_half(R0, ip + (hb + 4) * (HB * LIF_N));

        // consume hb+1, refill with hb+5
        consume_half(R1, V, sp + (hb + 1) * (HB * LIF_N));
        if (hb + 5 < NHB) load_half(R1, ip + (hb + 5) * (HB * LIF_N));

        // consume hb+2, refill with hb+6
        consume_half(R2, V, sp + (hb + 2) * (HB * LIF_N));
        if (hb + 6 < NHB) load_half(R2, ip + (hb + 6) * (HB * LIF_N));

        // consume hb+3, refill with hb+7
        consume_half(R3, V, sp + (hb + 3) * (HB * LIF_N));
        if (hb + 7 < NHB) load_half(R3, ip + (hb + 7) * (HB * LIF_N));
    }
}

extern "C" void kernel_launch(void* const* d_in, const int* in_sizes, int n_in,
                              void* d_out, int out_size) {
    const float* input = (const float*)d_in[0];
    float* spikes = (float*)d_out;

    const int grid = LIF_N / THREADS;   // 1024 CTAs x 64 threads = 65536 threads
    lif_kernel<<<grid, THREADS>>>(input, spikes);
}

// round 16
// speedup vs baseline: 1.0815x; 1.0815x over previous
#include <cuda_runtime.h>
#include <cuda_bf16.h>

// SingleLIFLayer: V <- V + (dt/tau)*(V_reset - V + I); spike = V >= V_th; reset.
// T=1024 steps x N=65536 neurons. Irreducible traffic: 256 MB R + 256 MB W.
//
// V12: ring-3 pipeline, occupancy-protected.
// R15 lesson: ring-4 ballooned to 168 regs -> HW cap 6 CTAs/SM < 6.92 supplied
// -> occupancy collapse (103 us). Constraint: regs <= 146 keeps 7 CTAs/SM.
// Ring-3 (48 buffer regs, ~110 total) raises per-warp outstanding loads to
// 32..48 (vs V10's 16..32) at UNCHANGED occupancy: ~69 KB in flight/SM vs the
// ~45 KB Little's-law requirement. Grain stays 16 (measured optimum 32/16/1 ->
// 92.0/88.5/89.9). __launch_bounds__(64,7) pins the reg budget to 146.

#define LIF_T   1024
#define LIF_N   65536
#define THREADS 64
#define HB      16                 // steps per burst (grain)
#define NHB     (LIF_T / HB)       // 64

__device__ __forceinline__ void load_half(float* __restrict__ dst,
                                          const float* __restrict__ src) {
    #pragma unroll
    for (int k = 0; k < HB; ++k)
        dst[k] = __ldcs(src + k * LIF_N);
}

__device__ __forceinline__ void consume_half(const float* __restrict__ cur,
                                             float& V, float* __restrict__ spb) {
    const float alpha = 0.05f;
    const float decay = 0.95f;
    const float vth   = 1.0f;
    #pragma unroll
    for (int k = 0; k < HB; ++k) {
        float c = alpha * cur[k];             // off-chain FMUL (hoists to load)
        V = fmaf(decay, V, c);                // chain: FFMA
        float s = (V >= vth) ? 1.0f : 0.0f;   // chain: FSET (data)
        __stcs(spb + k * LIF_N, s);
        V = fmaf(-s, V, V);                   // chain: FFMA (s==1 -> exactly 0)
    }
}

__global__ __launch_bounds__(THREADS, 7)   // reg budget 146 -> 7 CTAs/SM held
void lif_kernel(const float* __restrict__ in, float* __restrict__ out) {
    const int n = blockIdx.x * THREADS + threadIdx.x;   // neuron index

    float V = 0.0f;   // V_reset = 0

    const float* __restrict__ ip = in  + n;
    float*       __restrict__ sp = out + n;

    float R0[HB], R1[HB], R2[HB];

    // Prologue: fill ring with half-batches 0..2 (48 loads in flight).
    load_half(R0, ip + 0 * (HB * LIF_N));
    load_half(R1, ip + 1 * (HB * LIF_N));
    load_half(R2, ip + 2 * (HB * LIF_N));

    // Main loop: consumes hb 0..62 (21 iterations x 3). Load guards cover
    // the boundary; after the last iteration R0 holds half-batch 63.
    #pragma unroll 1
    for (int hb = 0; hb + 3 <= NHB; hb += 3) {
        consume_half(R0, V, sp + (hb + 0) * (HB * LIF_N));
        if (hb + 3 < NHB) load_half(R0, ip + (hb + 3) * (HB * LIF_N));

        consume_half(R1, V, sp + (hb + 1) * (HB * LIF_N));
        if (hb + 4 < NHB) load_half(R1, ip + (hb + 4) * (HB * LIF_N));

        consume_half(R2, V, sp + (hb + 2) * (HB * LIF_N));
        if (hb + 5 < NHB) load_half(R2, ip + (hb + 5) * (HB * LIF_N));
    }

    // Epilogue: NHB = 64 = 21*3 + 1 -> one half-batch left, in R0.
    consume_half(R0, V, sp + (NHB - 1) * (HB * LIF_N));
}

extern "C" void kernel_launch(void* const* d_in, const int* in_sizes, int n_in,
                              void* d_out, int out_size) {
    const float* input = (const float*)d_in[0];
    float* spikes = (float*)d_out;

    const int grid = LIF_N / THREADS;   // 1024 CTAs x 64 threads = 65536 threads
    lif_kernel<<<grid, THREADS>>>(input, spikes);
}

// round 17
// speedup vs baseline: 1.0863x; 1.0044x over previous
#include <cuda_runtime.h>
#include <cuda_bf16.h>

// SingleLIFLayer: V <- V + (dt/tau)*(V_reset - V + I); spike = V >= V_th; reset.
// T=1024 steps x N=65536 neurons. Irreducible traffic: 256 MB R + 256 MB W.
//
// V12 (ring-3, occupancy-protected) — RESUBMITTED VERBATIM as a
// reproducibility probe. R16 measured ncu=80.7us (best of session, 6.0 TB/s,
// regs=96, occ held) but scored=95.4us — a 14.7us scored-vs-ncu gap, out of
// family (no-split kernels gap 0.5-5.9us) and mechanically unexplained:
// V10's own scored loop sustains 6.09 TB/s, so a <6 TB/s sustained cap is
// falsified. Re-bench before concluding (rigor.md). If scored lands 85.5-88
// -> R16 was noise, this is the new best. If >=93 reproduces -> ring
// structure is replay-pathological; V10 (88.1) is the endpoint.
//
// Structure: three 16-step buffers, prefetch distance 3 (outstanding loads
// 32..48/warp ~ 69 KB/SM in flight vs ~45 KB Little's-law requirement),
// 16-load burst grain (measured optimum of 32/16/1 -> 92.0/88.5/89.9),
// 12-cyc serial chain, 1024x64 grid, __launch_bounds__(64,7) pins regs<=146.

#define LIF_T   1024
#define LIF_N   65536
#define THREADS 64
#define HB      16                 // steps per burst (grain)
#define NHB     (LIF_T / HB)       // 64

__device__ __forceinline__ void load_half(float* __restrict__ dst,
                                          const float* __restrict__ src) {
    #pragma unroll
    for (int k = 0; k < HB; ++k)
        dst[k] = __ldcs(src + k * LIF_N);
}

__device__ __forceinline__ void consume_half(const float* __restrict__ cur,
                                             float& V, float* __restrict__ spb) {
    const float alpha = 0.05f;
    const float decay = 0.95f;
    const float vth   = 1.0f;
    #pragma unroll
    for (int k = 0; k < HB; ++k) {
        float c = alpha * cur[k];             // off-chain FMUL (hoists to load)
        V = fmaf(decay, V, c);                // chain: FFMA
        float s = (V >= vth) ? 1.0f : 0.0f;   // chain: FSET (data)
        __stcs(spb + k * LIF_N, s);
        V = fmaf(-s, V, V);                   // chain: FFMA (s==1 -> exactly 0)
    }
}

__global__ __launch_bounds__(THREADS, 7)   // reg budget 146 -> 7 CTAs/SM held
void lif_kernel(const float* __restrict__ in, float* __restrict__ out) {
    const int n = blockIdx.x * THREADS + threadIdx.x;   // neuron index

    float V = 0.0f;   // V_reset = 0

    const float* __restrict__ ip = in  + n;
    float*       __restrict__ sp = out + n;

    float R0[HB], R1[HB], R2[HB];

    // Prologue: fill ring with half-batches 0..2 (48 loads in flight).
    load_half(R0, ip + 0 * (HB * LIF_N));
    load_half(R1, ip + 1 * (HB * LIF_N));
    load_half(R2, ip + 2 * (HB * LIF_N));

    // Main loop: consumes hb 0..62 (21 iterations x 3). Load guards cover
    // the boundary; after the last iteration R0 holds half-batch 63.
    #pragma unroll 1
    for (int hb = 0; hb + 3 <= NHB; hb += 3) {
        consume_half(R0, V, sp + (hb + 0) * (HB * LIF_N));
        if (hb + 3 < NHB) load_half(R0, ip + (hb + 3) * (HB * LIF_N));

        consume_half(R1, V, sp + (hb + 1) * (HB * LIF_N));
        if (hb + 4 < NHB) load_half(R1, ip + (hb + 4) * (HB * LIF_N));

        consume_half(R2, V, sp + (hb + 2) * (HB * LIF_N));
        if (hb + 5 < NHB) load_half(R2, ip + (hb + 5) * (HB * LIF_N));
    }

    // Epilogue: NHB = 64 = 21*3 + 1 -> one half-batch left, in R0.
    consume_half(R0, V, sp + (NHB - 1) * (HB * LIF_N));
}

extern "C" void kernel_launch(void* const* d_in, const int* in_sizes, int n_in,
                              void* d_out, int out_size) {
    const float* input = (const float*)d_in[0];
    float* spikes = (float*)d_out;

    const int grid = LIF_N / THREADS;   // 1024 CTAs x 64 threads = 65536 threads
    lif_kernel<<<grid, THREADS>>>(input, spikes);
}